// round 8
// baseline (speedup 1.0000x reference)
#include <cuda_runtime.h>
#include <math.h>

#define HW   96
#define NB   4
#define NT0  4
#define NT1  8
#define ZT   32
#define CIN  128          // NT0*ZT
#define TW   8
#define TH   2
#define PIXW (TW+4)       // 12
#define PIXH (TH+4)       // 6
#define NPIX (PIXW*PIXH)  // 72
#define PSTRIDE 140       // per-pixel smem stride in floats (4 groups of 32 + 4 pad each)

// transposed input scratch: [n][h][w][c], c = i*32 + z
__device__ float g_xt[NB*HW*HW*CIN];

// ---------------- Kernel A: (N,T0,Z,H,W) -> (N,H,W,C) transpose ----------------
__global__ __launch_bounds__(256) void k_transpose(const float* __restrict__ in)
{
    __shared__ float tile[32][33];
    int wt = blockIdx.x;          // 0..2  (w tile of 32)
    int h  = blockIdx.y;          // 0..95
    int ni = blockIdx.z;          // 0..15 = n*4+i
    int n = ni >> 2, i = ni & 3;
    int tx = threadIdx.x, ty = threadIdx.y;
    int w0 = wt * 32;
    #pragma unroll
    for (int k = 0; k < 4; k++) {
        int z = ty + 8*k;
        tile[z][tx] = in[(((n*NT0 + i)*ZT + z)*HW + h)*HW + w0 + tx];
    }
    __syncthreads();
    #pragma unroll
    for (int k = 0; k < 4; k++) {
        int w = w0 + ty + 8*k;
        g_xt[((n*HW + h)*HW + w)*CIN + i*32 + tx] = tile[tx][ty + 8*k];
    }
}

// ---------------- packed f32x2 helpers ----------------
__device__ __forceinline__ unsigned long long pack2(float x, float y) {
    unsigned long long r;
    asm("mov.b64 %0, {%1,%2};" : "=l"(r) : "f"(x), "f"(y));
    return r;
}
__device__ __forceinline__ void fma2(unsigned long long& d, unsigned long long a, unsigned long long b) {
    asm("fma.rn.f32x2 %0, %1, %2, %3;" : "=l"(d) : "l"(a), "l"(b), "l"(d));
}
__device__ __forceinline__ void unpack2(unsigned long long v, float& lo, float& hi) {
    asm("mov.b64 {%0,%1}, %2;" : "=f"(lo), "=f"(hi) : "l"(v));
}

// ---------------- Kernel B: fused conv + capsule transform + routing ----------------
__global__ __launch_bounds__(512) void k_caps(
    const float* __restrict__ Wc,   // (T0,5,5,1,T1) = 800
    const float* __restrict__ Wp,   // (T0,16,T1)    = 512
    const float* __restrict__ Wa,   // (T0,16,T1)    = 512
    const float* __restrict__ Ba,   // (T0,T1)       = 32
    float* __restrict__ out)        // (N,8,32,H,W)
{
    __shared__ __align__(16) float s_in[NPIX*PSTRIDE]; // 10080 floats; reused as s_out
    __shared__ float2 s_wcp[400];         // [(o*4+ta)*25 + k] = (Wc[o,k,ta], Wc[o,k,ta+4])
    __shared__ float s_mp[32*17];         // [lane=o*8+T][r*4+c] normalized W_pos
    __shared__ float s_ma[32*17];         // [lane][r*4+c] W_app
    __shared__ float s_ba[32];            // [lane]

    const int tid = threadIdx.x;
    const int n  = blockIdx.z;
    const int h0 = blockIdx.y * TH;
    const int w0 = blockIdx.x * TW;

    // ---- stage params ----
    // m[T][r][c] = Wp[i*128 + T*16 + r*4 + c].  tid = i*128+T*16+rc.
    {
        int i = tid >> 7, T = (tid >> 4) & 7, rc = tid & 15;
        s_mp[(i*8 + T)*17 + rc] = Wp[tid];
        s_ma[(i*8 + T)*17 + rc] = Wa[tid];
    }
    if (tid < 400) {
        int o = tid / 100, rem = tid - o*100;
        int ta = rem / 25, k = rem - ta*25;
        s_wcp[tid] = make_float2(Wc[o*200 + k*8 + ta], Wc[o*200 + k*8 + ta + 4]);
    }
    if (tid < 32)  s_ba[tid] = Ba[tid];

    // ---- stage input tile (halo 2, zero pad OOB) ----
    #pragma unroll
    for (int k = 0; k < 18; k++) {
        int L = tid + 512*k;            // 72*128 = 9216 total
        int pix = L >> 7, c = L & 127;
        int py = pix / PIXW, px = pix - py*PIXW;
        int gh = h0 - 2 + py, gw = w0 - 2 + px;
        float v = 0.f;
        if (gh >= 0 && gh < HW && gw >= 0 && gw < HW)
            v = g_xt[((n*HW + gh)*HW + gw)*CIN + c];
        s_in[pix*PSTRIDE + c + ((c >> 5) << 2)] = v;
    }
    __syncthreads();

    // ---- normalize W_pos columns: per (i,T,col): m /= sqrt(max(sum_r m^2,1e-12)) ----
    if (tid < 128) {
        int i = tid >> 5, T = (tid >> 2) & 7, cc = tid & 3;
        int base = (i*8 + T)*17;
        float s = 0.f;
        #pragma unroll
        for (int r = 0; r < 4; r++) { float v = s_mp[base + r*4 + cc]; s += v*v; }
        float inv = 1.f / sqrtf(fmaxf(s, 1e-12f));
        #pragma unroll
        for (int r = 0; r < 4; r++) s_mp[base + r*4 + cc] *= inv;
    }
    __syncthreads();

    // ---- per-warp pixel, per-lane (o,T) ----
    const int warp = tid >> 5, lane = tid & 31;
    const int py = warp >> 3, px = warp & 7;       // pixel in tile
    const int o = lane >> 3,  T = lane & 7;
    const int ta = T >> 1;                          // conv t1 (pos half); app half = ta+4
    const int zlo = (T & 1) << 4;
    const int wbase = (o*4 + ta)*25;

    // conv: u_spat[o][ta][zlo+j] (pos) and [o][ta+4][zlo+j] (app), j=0..15, f32x2-packed
    unsigned long long aP[8], aA[8];
    #pragma unroll
    for (int j = 0; j < 8; j++) { aP[j] = 0ull; aA[j] = 0ull; }

    #pragma unroll
    for (int ky = 0; ky < 5; ky++) {
        #pragma unroll
        for (int kx = 0; kx < 5; kx++) {
            int k = ky*5 + kx;
            float2 wab = s_wcp[wbase + k];
            unsigned long long wa2 = pack2(wab.x, wab.x);
            unsigned long long wb2 = pack2(wab.y, wab.y);
            const ulonglong2* pin = reinterpret_cast<const ulonglong2*>(
                s_in + ((py + ky)*PIXW + (px + kx))*PSTRIDE + o*36 + zlo);
            #pragma unroll
            for (int jj = 0; jj < 4; jj++) {
                ulonglong2 x2 = pin[jj];
                fma2(aP[2*jj],   x2.x, wa2);
                fma2(aP[2*jj+1], x2.y, wa2);
                fma2(aA[2*jj],   x2.x, wb2);
                fma2(aA[2*jj+1], x2.y, wb2);
            }
        }
    }

    float up[16], ua[16];
    #pragma unroll
    for (int j = 0; j < 8; j++) {
        unpack2(aP[j], up[2*j], up[2*j+1]);
        unpack2(aA[j], ua[2*j], ua[2*j+1]);
    }

    // ---- capsule transform: u_hat[z] ----
    float u[32];
    {
        float mm[16];
        #pragma unroll
        for (int q = 0; q < 16; q++) mm[q] = s_mp[lane*17 + q];
        mm[12] += (float)(w0 + px) * (1.f/96.f);   // coord add: M[3][0] += x/W
        mm[13] += (float)(h0 + py) * (1.f/96.f);   //            M[3][1] += y/H
        #pragma unroll
        for (int a = 0; a < 4; a++) {
            float r0 = up[4*a+0], r1 = up[4*a+1], r2 = up[4*a+2], r3 = up[4*a+3];
            #pragma unroll
            for (int b = 0; b < 4; b++)
                u[a*4+b] = r0*mm[b] + r1*mm[4+b] + r2*mm[8+b] + r3*mm[12+b];
        }
        float bap = s_ba[lane];
        #pragma unroll
        for (int q = 0; q < 16; q++) mm[q] = s_ma[lane*17 + q];
        #pragma unroll
        for (int a = 0; a < 4; a++) {
            float r0 = ua[4*a+0]+bap, r1 = ua[4*a+1]+bap, r2 = ua[4*a+2]+bap, r3 = ua[4*a+3]+bap;
            #pragma unroll
            for (int b = 0; b < 4; b++)
                u[16 + a*4 + b] = r0*mm[b] + r1*mm[4+b] + r2*mm[8+b] + r3*mm[12+b];
        }
    }

    __syncthreads();                    // all warps done with s_in
    float* s_out = s_in;                // reuse as output stage [pix*265 + T*33 + z]

    // ---- dynamic routing (3 passes; last writes v) ----
    float blog = 0.f;
    #pragma unroll
    for (int it = 0; it < 3; it++) {
        float r = 1.f / (1.f + __expf(-blog));
        float p[32];
        #pragma unroll
        for (int z = 0; z < 32; z++) {
            float v = u[z] * r;
            v += __shfl_xor_sync(0xffffffffu, v, 8);
            v += __shfl_xor_sync(0xffffffffu, v, 16);
            p[z] = v;                   // p[T][z], identical across o-lanes of same T
        }
        float mx = fabsf(p[0]);
        #pragma unroll
        for (int z = 1; z < 16; z++) mx = fmaxf(mx, fabsf(p[z]));
        float n2 = 0.f;
        #pragma unroll
        for (int z = 16; z < 32; z++) n2 = fmaf(p[z], p[z], n2);
        float sp = 1.f / mx;                                  // psquash scale
        float nn = sqrtf(n2 + 1e-9f);
        float sa = n2 / ((1.f + n2) * nn);                    // matwo squash scale
        if (it < 2) {
            float dp = 0.f, da = 0.f;
            #pragma unroll
            for (int z = 0;  z < 16; z++) dp = fmaf(u[z], p[z], dp);
            #pragma unroll
            for (int z = 16; z < 32; z++) da = fmaf(u[z], p[z], da);
            blog += (dp * sp) * (da * sa);
        } else if (o == 0) {
            #pragma unroll
            for (int z = 0; z < 32; z++)
                s_out[warp*265 + T*33 + z] = p[z] * (z < 16 ? sp : sa);
        }
    }
    __syncthreads();

    // ---- coalesced output write: out[n][t][z][h][w] ----
    #pragma unroll
    for (int k = 0; k < 8; k++) {
        int e = tid + k*512;            // 16 pixels x 256 (t,z)
        int pix = e & 15, tz = e >> 4;
        int t = tz >> 5, z = tz & 31;
        int gh = h0 + (pix >> 3), gw = w0 + (pix & 7);
        out[(((n*8 + t)*32 + z)*HW + gh)*HW + gw] = s_out[pix*265 + t*33 + z];
    }
}

extern "C" void kernel_launch(void* const* d_in, const int* in_sizes, int n_in,
                              void* d_out, int out_size)
{
    (void)in_sizes; (void)n_in; (void)out_size;
    const float* x  = (const float*)d_in[0];
    const float* Wc = (const float*)d_in[1];
    const float* Wp = (const float*)d_in[2];
    const float* Wa = (const float*)d_in[3];
    const float* Ba = (const float*)d_in[4];
    float* out = (float*)d_out;

    dim3 gA(3, 96, 16), bA(32, 8);
    k_transpose<<<gA, bA>>>(x);

    dim3 gB(HW/TW, HW/TH, NB);          // (12, 48, 4)
    k_caps<<<gB, 512>>>(Wc, Wp, Wa, Ba, out);
}

// round 10
// speedup vs baseline: 1.2323x; 1.2323x over previous
#include <cuda_runtime.h>
#include <math.h>

#define HW   96
#define NB   4
#define NT0  4
#define NT1  8
#define ZT   32
#define CIN  128          // NT0*ZT
#define TW   4
#define TH   2
#define PIXW (TW+4)       // 8
#define PIXH (TH+4)       // 6
#define NPIX (PIXW*PIXH)  // 48
#define PSTRIDE 140       // per-pixel smem stride in floats (4 groups of 32 + 4 pad each)
#define NTHR 256

// transposed input scratch: [n][h][w][c], c = i*32 + z
__device__ float g_xt[NB*HW*HW*CIN];

// ---------------- Kernel A: (N,T0,Z,H,W) -> (N,H,W,C) transpose ----------------
__global__ __launch_bounds__(256) void k_transpose(const float* __restrict__ in)
{
    __shared__ float tile[32][33];
    int wt = blockIdx.x;          // 0..2  (w tile of 32)
    int h  = blockIdx.y;          // 0..95
    int ni = blockIdx.z;          // 0..15 = n*4+i
    int n = ni >> 2, i = ni & 3;
    int tx = threadIdx.x, ty = threadIdx.y;
    int w0 = wt * 32;
    #pragma unroll
    for (int k = 0; k < 4; k++) {
        int z = ty + 8*k;
        tile[z][tx] = in[(((n*NT0 + i)*ZT + z)*HW + h)*HW + w0 + tx];
    }
    __syncthreads();
    #pragma unroll
    for (int k = 0; k < 4; k++) {
        int w = w0 + ty + 8*k;
        g_xt[((n*HW + h)*HW + w)*CIN + i*32 + tx] = tile[tx][ty + 8*k];
    }
}

// ---------------- packed f32x2 helpers ----------------
__device__ __forceinline__ unsigned long long pack2(float x, float y) {
    unsigned long long r;
    asm("mov.b64 %0, {%1,%2};" : "=l"(r) : "f"(x), "f"(y));
    return r;
}
__device__ __forceinline__ void fma2(unsigned long long& d, unsigned long long a, unsigned long long b) {
    asm("fma.rn.f32x2 %0, %1, %2, %3;" : "=l"(d) : "l"(a), "l"(b), "l"(d));
}
__device__ __forceinline__ void unpack2(unsigned long long v, float& lo, float& hi) {
    asm("mov.b64 {%0,%1}, %2;" : "=f"(lo), "=f"(hi) : "l"(v));
}

// ---------------- Kernel B: fused conv + capsule transform + routing ----------------
__global__ __launch_bounds__(NTHR, 3) void k_caps(
    const float* __restrict__ Wc,   // (T0,5,5,1,T1) = 800
    const float* __restrict__ Wp,   // (T0,16,T1)    = 512
    const float* __restrict__ Wa,   // (T0,16,T1)    = 512
    const float* __restrict__ Ba,   // (T0,T1)       = 32
    float* __restrict__ out)        // (N,8,32,H,W)
{
    __shared__ __align__(16) float s_in[NPIX*PSTRIDE]; // 48*140 = 6720 floats; reused as s_out
    __shared__ float2 s_wcp[400];         // [(o*4+ta)*25 + k] = (Wc[o,k,ta], Wc[o,k,ta+4])
    __shared__ float s_mp[32*17];         // [lane=o*8+T][r*4+c] normalized W_pos
    __shared__ float s_ma[32*17];         // [lane][r*4+c] W_app
    __shared__ float s_ba[32];            // [lane]

    const int tid = threadIdx.x;
    const int n  = blockIdx.z;
    const int h0 = blockIdx.y * TH;
    const int w0 = blockIdx.x * TW;

    // ---- stage params ----
    // m[T][r][c] = Wp[i*128 + T*16 + r*4 + c].
    #pragma unroll
    for (int k = 0; k < 2; k++) {
        int idx = tid + NTHR*k;
        int i = idx >> 7, T = (idx >> 4) & 7, rc = idx & 15;
        s_mp[(i*8 + T)*17 + rc] = Wp[idx];
        s_ma[(i*8 + T)*17 + rc] = Wa[idx];
    }
    #pragma unroll
    for (int k = 0; k < 2; k++) {
        int idx = tid + NTHR*k;
        if (idx < 400) {
            int o = idx / 100, rem = idx - o*100;
            int ta = rem / 25, kk = rem - ta*25;
            s_wcp[idx] = make_float2(Wc[o*200 + kk*8 + ta], Wc[o*200 + kk*8 + ta + 4]);
        }
    }
    if (tid < 32)  s_ba[tid] = Ba[tid];

    // ---- stage input tile (halo 2, zero pad OOB), float4 ----
    #pragma unroll
    for (int k = 0; k < 6; k++) {
        int L = tid + NTHR*k;           // 48*32 = 1536 float4 total
        int pix = L >> 5, c4 = L & 31;
        int c = c4 << 2;
        int py = pix >> 3, px = pix & 7;
        int gh = h0 - 2 + py, gw = w0 - 2 + px;
        float4 v = make_float4(0.f, 0.f, 0.f, 0.f);
        if (gh >= 0 && gh < HW && gw >= 0 && gw < HW)
            v = *reinterpret_cast<const float4*>(&g_xt[((n*HW + gh)*HW + gw)*CIN + c]);
        *reinterpret_cast<float4*>(&s_in[pix*PSTRIDE + c + ((c >> 5) << 2)]) = v;
    }
    __syncthreads();

    // ---- normalize W_pos columns: per (i,T,col): m /= sqrt(max(sum_r m^2,1e-12)) ----
    if (tid < 128) {
        int i = tid >> 5, T = (tid >> 2) & 7, cc = tid & 3;
        int base = (i*8 + T)*17;
        float s = 0.f;
        #pragma unroll
        for (int r = 0; r < 4; r++) { float v = s_mp[base + r*4 + cc]; s += v*v; }
        float inv = 1.f / sqrtf(fmaxf(s, 1e-12f));
        #pragma unroll
        for (int r = 0; r < 4; r++) s_mp[base + r*4 + cc] *= inv;
    }
    __syncthreads();

    // ---- per-warp pixel, per-lane (o,T) ----
    const int warp = tid >> 5, lane = tid & 31;
    const int py = warp >> 2, px = warp & 3;       // pixel in 4x2 tile
    const int o = lane >> 3,  T = lane & 7;
    const int ta = T >> 1;                          // conv t1 (pos half); app half = ta+4
    const int zlo = (T & 1) << 4;
    const int wbase = (o*4 + ta)*25;

    // conv: u_spat[o][ta][zlo+j] (pos) and [o][ta+4][zlo+j] (app), j=0..15, f32x2-packed
    unsigned long long aP[8], aA[8];
    #pragma unroll
    for (int j = 0; j < 8; j++) { aP[j] = 0ull; aA[j] = 0ull; }

    #pragma unroll
    for (int ky = 0; ky < 5; ky++) {
        #pragma unroll
        for (int kx = 0; kx < 5; kx++) {
            int k = ky*5 + kx;
            float2 wab = s_wcp[wbase + k];
            unsigned long long wa2 = pack2(wab.x, wab.x);
            unsigned long long wb2 = pack2(wab.y, wab.y);
            const ulonglong2* pin = reinterpret_cast<const ulonglong2*>(
                s_in + ((py + ky)*PIXW + (px + kx))*PSTRIDE + o*36 + zlo);
            #pragma unroll
            for (int jj = 0; jj < 4; jj++) {
                ulonglong2 x2 = pin[jj];
                fma2(aP[2*jj],   x2.x, wa2);
                fma2(aP[2*jj+1], x2.y, wa2);
                fma2(aA[2*jj],   x2.x, wb2);
                fma2(aA[2*jj+1], x2.y, wb2);
            }
        }
    }

    float up[16], ua[16];
    #pragma unroll
    for (int j = 0; j < 8; j++) {
        unpack2(aP[j], up[2*j], up[2*j+1]);
        unpack2(aA[j], ua[2*j], ua[2*j+1]);
    }

    // ---- capsule transform: u_hat[z] ----
    float u[32];
    {
        float mm[16];
        #pragma unroll
        for (int q = 0; q < 16; q++) mm[q] = s_mp[lane*17 + q];
        mm[12] += (float)(w0 + px) * (1.f/96.f);   // coord add: M[3][0] += x/W
        mm[13] += (float)(h0 + py) * (1.f/96.f);   //            M[3][1] += y/H
        #pragma unroll
        for (int a = 0; a < 4; a++) {
            float r0 = up[4*a+0], r1 = up[4*a+1], r2 = up[4*a+2], r3 = up[4*a+3];
            #pragma unroll
            for (int b = 0; b < 4; b++)
                u[a*4+b] = r0*mm[b] + r1*mm[4+b] + r2*mm[8+b] + r3*mm[12+b];
        }
        float bap = s_ba[lane];
        #pragma unroll
        for (int q = 0; q < 16; q++) mm[q] = s_ma[lane*17 + q];
        #pragma unroll
        for (int a = 0; a < 4; a++) {
            float r0 = ua[4*a+0]+bap, r1 = ua[4*a+1]+bap, r2 = ua[4*a+2]+bap, r3 = ua[4*a+3]+bap;
            #pragma unroll
            for (int b = 0; b < 4; b++)
                u[16 + a*4 + b] = r0*mm[b] + r1*mm[4+b] + r2*mm[8+b] + r3*mm[12+b];
        }
    }

    __syncthreads();                    // all warps done with s_in
    float* s_out = s_in;                // reuse as output stage [pix*265 + T*33 + z]

    // ---- dynamic routing (3 passes; last writes v) ----
    float blog = 0.f;
    #pragma unroll
    for (int it = 0; it < 3; it++) {
        float r = 1.f / (1.f + __expf(-blog));
        float p[32];
        #pragma unroll
        for (int z = 0; z < 32; z++) {
            float v = u[z] * r;
            v += __shfl_xor_sync(0xffffffffu, v, 8);
            v += __shfl_xor_sync(0xffffffffu, v, 16);
            p[z] = v;                   // p[T][z], identical across o-lanes of same T
        }
        float mx = fabsf(p[0]);
        #pragma unroll
        for (int z = 1; z < 16; z++) mx = fmaxf(mx, fabsf(p[z]));
        float n2 = 0.f;
        #pragma unroll
        for (int z = 16; z < 32; z++) n2 = fmaf(p[z], p[z], n2);
        float sp = 1.f / mx;                                  // psquash scale
        float nn = sqrtf(n2 + 1e-9f);
        float sa = n2 / ((1.f + n2) * nn);                    // matwo squash scale
        if (it < 2) {
            float dp = 0.f, da = 0.f;
            #pragma unroll
            for (int z = 0;  z < 16; z++) dp = fmaf(u[z], p[z], dp);
            #pragma unroll
            for (int z = 16; z < 32; z++) da = fmaf(u[z], p[z], da);
            blog += (dp * sp) * (da * sa);
        } else if (o == 0) {
            #pragma unroll
            for (int z = 0; z < 32; z++)
                s_out[warp*265 + T*33 + z] = p[z] * (z < 16 ? sp : sa);
        }
    }
    __syncthreads();

    // ---- output write: out[n][t][z][h][w] (16B runs of w) ----
    #pragma unroll
    for (int k = 0; k < 8; k++) {
        int e = tid + k*NTHR;           // 8 pixels x 256 (t,z)
        int pix = e & 7, tz = e >> 3;
        int t = tz >> 5, z = tz & 31;
        int gh = h0 + (pix >> 2), gw = w0 + (pix & 3);
        out[(((n*8 + t)*32 + z)*HW + gh)*HW + gw] = s_out[pix*265 + t*33 + z];
    }
}

extern "C" void kernel_launch(void* const* d_in, const int* in_sizes, int n_in,
                              void* d_out, int out_size)
{
    (void)in_sizes; (void)n_in; (void)out_size;
    const float* x  = (const float*)d_in[0];
    const float* Wc = (const float*)d_in[1];
    const float* Wp = (const float*)d_in[2];
    const float* Wa = (const float*)d_in[3];
    const float* Ba = (const float*)d_in[4];
    float* out = (float*)d_out;

    dim3 gA(3, 96, 16), bA(32, 8);
    k_transpose<<<gA, bA>>>(x);

    dim3 gB(HW/TW, HW/TH, NB);          // (24, 48, 4)
    k_caps<<<gB, NTHR>>>(Wc, Wp, Wa, Ba, out);
}